// round 3
// baseline (speedup 1.0000x reference)
#include <cuda_runtime.h>
#include <cstdint>

#define B_  16
#define N_  4096
#define S_  1024
#define C_  256
#define M_  (B_ * N_)   // 65536

// ---------------- scratch (no allocations allowed) ----------------
__device__ float g_interp[(size_t)M_ * C_];   // (B*N, 256) interpolated feats
__device__ float g_y[(size_t)M_ * C_];        // GEMM1 output / hidden
__device__ int   g_idx[M_ * 3];
__device__ float g_w[M_ * 3];
__device__ float g_psum[128 * 256];
__device__ float g_psq [128 * 256];
__device__ float g_scale[256];
__device__ float g_shift[256];

// ---------------- packed f32x2 helpers ----------------
__device__ __forceinline__ unsigned long long pack2(float lo, float hi) {
    unsigned long long r;
    asm("mov.b64 %0, {%1, %2};" : "=l"(r) : "f"(lo), "f"(hi));
    return r;
}
__device__ __forceinline__ void unpack2(unsigned long long v, float& lo, float& hi) {
    asm("mov.b64 {%0, %1}, %2;" : "=f"(lo), "=f"(hi) : "l"(v));
}
#define FFMA2(acc, a, bb) asm("fma.rn.f32x2 %0, %1, %2, %0;" : "+l"(acc) : "l"(a), "l"(bb))

// ---------------- 3-NN (idx + weights) ----------------
__global__ void knn_kernel(const float* __restrict__ xyz1,
                           const float* __restrict__ xyz2)
{
    __shared__ float sx[S_], sy[S_], sz[S_], ss[S_];
    int b = blockIdx.y;
    const float* X2 = xyz2 + (size_t)b * S_ * 3;
    for (int i = threadIdx.x; i < S_; i += blockDim.x) {
        float x = X2[i*3+0], y = X2[i*3+1], z = X2[i*3+2];
        sx[i] = x; sy[i] = y; sz[i] = z;
        ss[i] = x*x + y*y + z*z;
    }
    __syncthreads();

    int n = blockIdx.x * blockDim.x + threadIdx.x;
    const float* p = xyz1 + ((size_t)b * N_ + n) * 3;
    float x1 = p[0], y1 = p[1], z1 = p[2];
    float s1 = x1*x1 + y1*y1 + z1*z1;

    float d0 = 3.4e38f, d1 = 3.4e38f, d2 = 3.4e38f;
    int   i0 = 0, i1 = 0, i2 = 0;
    #pragma unroll 4
    for (int s = 0; s < S_; s++) {
        float dot = fmaf(x1, sx[s], fmaf(y1, sy[s], z1 * sz[s]));
        float d   = fmaf(-2.0f, dot, s1 + ss[s]);   // matches ref: |x1|^2+|x2|^2-2<x1,x2>
        if (d < d2) {
            if (d < d1) {
                d2 = d1; i2 = i1;
                if (d < d0) { d1 = d0; i1 = i0; d0 = d; i0 = s; }
                else        { d1 = d;  i1 = s; }
            } else { d2 = d; i2 = s; }
        }
    }
    float r0 = 1.0f / (d0 + 1e-8f);
    float r1 = 1.0f / (d1 + 1e-8f);
    float r2 = 1.0f / (d2 + 1e-8f);
    float inv = 1.0f / (r0 + r1 + r2);
    size_t o = ((size_t)b * N_ + n) * 3;
    g_idx[o+0] = i0; g_idx[o+1] = i1; g_idx[o+2] = i2;
    g_w[o+0] = r0 * inv; g_w[o+1] = r1 * inv; g_w[o+2] = r2 * inv;
}

// ---------------- gather + weighted interpolation ----------------
__global__ void interp_kernel(const float* __restrict__ points2)
{
    int lane = threadIdx.x & 31;
    int warp = threadIdx.x >> 5;
    size_t ng = (size_t)blockIdx.x * 8 + warp;     // global point id, 0..65535
    int b = (int)(ng >> 12);

    const int*   id = g_idx + ng * 3;
    const float* wt = g_w   + ng * 3;
    int a0 = id[0], a1 = id[1], a2 = id[2];
    float w0 = wt[0], w1 = wt[1], w2 = wt[2];

    const float* P  = points2 + (size_t)b * S_ * C_;
    const float* p0 = P + (size_t)a0 * C_;
    const float* p1 = P + (size_t)a1 * C_;
    const float* p2 = P + (size_t)a2 * C_;
    float* out = g_interp + ng * C_;

    #pragma unroll
    for (int c = lane * 4; c < C_; c += 128) {
        float4 v0 = *(const float4*)(p0 + c);
        float4 v1 = *(const float4*)(p1 + c);
        float4 v2 = *(const float4*)(p2 + c);
        float4 o;
        o.x = w0*v0.x + w1*v1.x + w2*v2.x;
        o.y = w0*v0.y + w1*v1.y + w2*v2.y;
        o.z = w0*v0.z + w1*v1.z + w2*v2.z;
        o.w = w0*v0.w + w1*v1.w + w2*v2.w;
        *(float4*)(out + c) = o;
    }
}

// ---------------- SGEMM via packed fma.rn.f32x2 ----------------
// Y[m, n] = sum_k A[m, k] * W[n, k],  A split across two 256-col sources.
// MODE 1: A0 = points1 (ext), A1 = g_interp, Y = g_y       (K = 512, split = 256)
// MODE 2: A0 = g_y (device global), Y = Yext/d_out         (K = 256)
template<int MODE>
__global__ __launch_bounds__(256, 2)
void gemm_kernel(const float* __restrict__ A0ext,
                 const float* __restrict__ W,
                 float* Yext, int K, int split)
{
    __shared__ __align__(16) float As[2][8][128];
    __shared__ __align__(16) float Bs[2][8][128];

    const float* A0 = (MODE == 1) ? A0ext : (const float*)g_y;   // FIX: MODE 2 reads g_y
    const float* A1 = (MODE == 1) ? (const float*)g_interp : (const float*)g_y;
    float*       Y  = (MODE == 1) ? (float*)g_y : Yext;

    const int tid  = threadIdx.x;
    const int tx   = tid & 15;
    const int ty   = tid >> 4;
    const int lrow = tid >> 1;            // 0..127
    const int lk4  = (tid & 1) * 4;       // 0 or 4
    const int m0   = blockIdx.y * 128;
    const int n0   = blockIdx.x * 128;

    unsigned long long acc[8][4];
    #pragma unroll
    for (int i = 0; i < 8; i++)
        #pragma unroll
        for (int j = 0; j < 4; j++) acc[i][j] = 0ULL;

    // prologue: tile kt=0 (always < split)
    {
        float4 av = *(const float4*)(A0 + (size_t)(m0 + lrow) * C_ + lk4);
        float4 bv = *(const float4*)(W  + (size_t)(n0 + lrow) * K  + lk4);
        As[0][lk4+0][lrow] = av.x; As[0][lk4+1][lrow] = av.y;
        As[0][lk4+2][lrow] = av.z; As[0][lk4+3][lrow] = av.w;
        Bs[0][lk4+0][lrow] = bv.x; Bs[0][lk4+1][lrow] = bv.y;
        Bs[0][lk4+2][lrow] = bv.z; Bs[0][lk4+3][lrow] = bv.w;
    }
    __syncthreads();

    int buf = 0;
    for (int kt = 0; kt < K; kt += 8) {
        int ktn = kt + 8;
        bool nxt = ktn < K;
        float4 av, bv;
        if (nxt) {
            const float* Ab; int kk0;
            if (ktn < split) { Ab = A0; kk0 = ktn; }
            else             { Ab = A1; kk0 = ktn - split; }
            av = *(const float4*)(Ab + (size_t)(m0 + lrow) * C_ + kk0 + lk4);
            bv = *(const float4*)(W  + (size_t)(n0 + lrow) * K  + ktn + lk4);
        }

        #pragma unroll
        for (int kk = 0; kk < 8; kk++) {
            float4 a0v = *(const float4*)&As[buf][kk][ty*8];
            float4 a1v = *(const float4*)&As[buf][kk][ty*8+4];
            float4 b0v = *(const float4*)&Bs[buf][kk][tx*8];
            float4 b1v = *(const float4*)&Bs[buf][kk][tx*8+4];
            unsigned long long bp0 = pack2(b0v.x, b0v.y);
            unsigned long long bp1 = pack2(b0v.z, b0v.w);
            unsigned long long bp2 = pack2(b1v.x, b1v.y);
            unsigned long long bp3 = pack2(b1v.z, b1v.w);
            float a[8] = {a0v.x, a0v.y, a0v.z, a0v.w, a1v.x, a1v.y, a1v.z, a1v.w};
            #pragma unroll
            for (int i = 0; i < 8; i++) {
                unsigned long long ap = pack2(a[i], a[i]);
                FFMA2(acc[i][0], ap, bp0);
                FFMA2(acc[i][1], ap, bp1);
                FFMA2(acc[i][2], ap, bp2);
                FFMA2(acc[i][3], ap, bp3);
            }
        }

        if (nxt) {
            int nb = buf ^ 1;
            As[nb][lk4+0][lrow] = av.x; As[nb][lk4+1][lrow] = av.y;
            As[nb][lk4+2][lrow] = av.z; As[nb][lk4+3][lrow] = av.w;
            Bs[nb][lk4+0][lrow] = bv.x; Bs[nb][lk4+1][lrow] = bv.y;
            Bs[nb][lk4+2][lrow] = bv.z; Bs[nb][lk4+3][lrow] = bv.w;
            __syncthreads();
            buf = nb;
        }
    }

    // epilogue
    #pragma unroll
    for (int i = 0; i < 8; i++) {
        float o[8];
        #pragma unroll
        for (int j = 0; j < 4; j++) unpack2(acc[i][j], o[2*j], o[2*j+1]);
        float* yp = Y + (size_t)(m0 + ty*8 + i) * 256 + n0 + tx*8;
        *(float4*)(yp)     = make_float4(o[0], o[1], o[2], o[3]);
        *(float4*)(yp + 4) = make_float4(o[4], o[5], o[6], o[7]);
    }
}

// ---------------- deterministic BatchNorm stats ----------------
template<bool USE_G>
__global__ void stats_partial_kernel(const float* Yext)
{
    const float* Y = USE_G ? (const float*)g_y : Yext;
    int c = threadIdx.x;                       // 256 channels
    size_t r0 = (size_t)blockIdx.x * 512;
    const float* p = Y + r0 * 256 + c;
    float s = 0.f, s2 = 0.f;
    for (int i = 0; i < 512; i++) {
        float v = p[(size_t)i * 256];
        s += v;
        s2 = fmaf(v, v, s2);
    }
    g_psum[blockIdx.x * 256 + c] = s;
    g_psq [blockIdx.x * 256 + c] = s2;
}

__global__ void stats_finalize_kernel(const float* __restrict__ gamma,
                                      const float* __restrict__ beta)
{
    int c = threadIdx.x;
    float s = 0.f, s2 = 0.f;
    for (int i = 0; i < 128; i++) {
        s  += g_psum[i * 256 + c];
        s2 += g_psq [i * 256 + c];
    }
    const float invM = 1.0f / 65536.0f;
    float mu   = s * invM;
    float var  = fmaf(-mu, mu, s2 * invM);
    float rstd = rsqrtf(var + 1e-5f);
    float sc   = rstd * gamma[c];
    g_scale[c] = sc;
    g_shift[c] = fmaf(-mu, sc, beta[c]);
}

template<bool USE_G>
__global__ void norm_relu_kernel(float* Yext)
{
    float* Y = USE_G ? (float*)g_y : Yext;
    size_t i = (size_t)blockIdx.x * blockDim.x + threadIdx.x;  // float4 index
    int cg = (int)(i & 63) * 4;
    float4 v = *((float4*)Y + i);
    v.x = fmaxf(fmaf(v.x, __ldg(&g_scale[cg+0]), __ldg(&g_shift[cg+0])), 0.f);
    v.y = fmaxf(fmaf(v.y, __ldg(&g_scale[cg+1]), __ldg(&g_shift[cg+1])), 0.f);
    v.z = fmaxf(fmaf(v.z, __ldg(&g_scale[cg+2]), __ldg(&g_shift[cg+2])), 0.f);
    v.w = fmaxf(fmaf(v.w, __ldg(&g_scale[cg+3]), __ldg(&g_shift[cg+3])), 0.f);
    *((float4*)Y + i) = v;
}

// ---------------- launch ----------------
extern "C" void kernel_launch(void* const* d_in, const int* in_sizes, int n_in,
                              void* d_out, int out_size)
{
    const float* xyz1    = (const float*)d_in[0];
    const float* xyz2    = (const float*)d_in[1];
    const float* points1 = (const float*)d_in[2];
    const float* points2 = (const float*)d_in[3];
    const float* w1      = (const float*)d_in[4];
    const float* g1      = (const float*)d_in[5];
    const float* b1      = (const float*)d_in[6];
    const float* w2      = (const float*)d_in[7];
    const float* g2      = (const float*)d_in[8];
    const float* b2      = (const float*)d_in[9];
    float* out = (float*)d_out;

    knn_kernel<<<dim3(N_ / 256, B_), 256>>>(xyz1, xyz2);
    interp_kernel<<<M_ / 8, 256>>>(points2);

    gemm_kernel<1><<<dim3(2, 512), 256>>>(points1, w1, nullptr, 512, 256);
    stats_partial_kernel<true><<<128, 256>>>(nullptr);
    stats_finalize_kernel<<<1, 256>>>(g1, b1);
    norm_relu_kernel<true><<<16384, 256>>>(nullptr);

    gemm_kernel<2><<<dim3(2, 512), 256>>>(nullptr, w2, out, 256, 256);
    stats_partial_kernel<false><<<128, 256>>>(out);
    stats_finalize_kernel<<<1, 256>>>(g2, b2);
    norm_relu_kernel<false><<<16384, 256>>>(out);
}

// round 5
// speedup vs baseline: 2.0130x; 2.0130x over previous
#include <cuda_runtime.h>
#include <cstdint>

#define B_  16
#define N_  4096
#define S_  1024
#define C_  256
#define M_  (B_ * N_)   // 65536

// ---------------- scratch (no allocations allowed) ----------------
__device__ float g_interp[(size_t)M_ * C_];   // (B*N, 256) interpolated feats
__device__ float g_y[(size_t)M_ * C_];        // GEMM1 output (pre-BN hidden)
__device__ int   g_idx[M_ * 3];
__device__ float g_w[M_ * 3];
__device__ float g_psum[512 * 256];
__device__ float g_psq [512 * 256];
__device__ float g_scale[256];
__device__ float g_shift[256];

// ---------------- PTX helpers (family-portable, sm_80+) ----------------
__device__ __forceinline__ uint32_t smem_u32(const void* p) {
    uint32_t a;
    asm("{ .reg .u64 t; cvta.to.shared.u64 t, %1; cvt.u32.u64 %0, t; }" : "=r"(a) : "l"(p));
    return a;
}
__device__ __forceinline__ uint32_t f2tf(float x) {
    uint32_t r; asm("cvt.rna.tf32.f32 %0, %1;" : "=r"(r) : "f"(x)); return r;
}
#define CP16(dst, src) \
    asm volatile("cp.async.cg.shared.global [%0], [%1], 16;" :: "r"(dst), "l"(src) : "memory")
#define CP_COMMIT() asm volatile("cp.async.commit_group;" ::: "memory")
#define CP_WAIT(N)  asm volatile("cp.async.wait_group %0;" :: "n"(N) : "memory")

#define MMA_TF32(c, a, b) \
    asm volatile("mma.sync.aligned.m16n8k8.row.col.f32.tf32.tf32.f32 " \
        "{%0,%1,%2,%3}, {%4,%5,%6,%7}, {%8,%9}, {%0,%1,%2,%3};" \
        : "+f"((c)[0]), "+f"((c)[1]), "+f"((c)[2]), "+f"((c)[3]) \
        : "r"((a)[0]), "r"((a)[1]), "r"((a)[2]), "r"((a)[3]), \
          "r"((b)[0]), "r"((b)[1]))

// ---------------- 3-NN (idx + weights) ----------------
__global__ void knn_kernel(const float* __restrict__ xyz1,
                           const float* __restrict__ xyz2)
{
    __shared__ float sx[S_], sy[S_], sz[S_], ss[S_];
    int b = blockIdx.y;
    const float* X2 = xyz2 + (size_t)b * S_ * 3;
    for (int i = threadIdx.x; i < S_; i += blockDim.x) {
        float x = X2[i*3+0], y = X2[i*3+1], z = X2[i*3+2];
        sx[i] = x; sy[i] = y; sz[i] = z;
        ss[i] = x*x + y*y + z*z;
    }
    __syncthreads();

    int n = blockIdx.x * blockDim.x + threadIdx.x;
    const float* p = xyz1 + ((size_t)b * N_ + n) * 3;
    float x1 = p[0], y1 = p[1], z1 = p[2];
    float s1 = x1*x1 + y1*y1 + z1*z1;

    float d0 = 3.4e38f, d1 = 3.4e38f, d2 = 3.4e38f;
    int   i0 = 0, i1 = 0, i2 = 0;
    #pragma unroll 4
    for (int s = 0; s < S_; s++) {
        float dot = fmaf(x1, sx[s], fmaf(y1, sy[s], z1 * sz[s]));
        float d   = fmaf(-2.0f, dot, s1 + ss[s]);
        if (d < d2) {
            if (d < d1) {
                d2 = d1; i2 = i1;
                if (d < d0) { d1 = d0; i1 = i0; d0 = d; i0 = s; }
                else        { d1 = d;  i1 = s; }
            } else { d2 = d; i2 = s; }
        }
    }
    float r0 = 1.0f / (d0 + 1e-8f);
    float r1 = 1.0f / (d1 + 1e-8f);
    float r2 = 1.0f / (d2 + 1e-8f);
    float inv = 1.0f / (r0 + r1 + r2);
    size_t o = ((size_t)b * N_ + n) * 3;
    g_idx[o+0] = i0; g_idx[o+1] = i1; g_idx[o+2] = i2;
    g_w[o+0] = r0 * inv; g_w[o+1] = r1 * inv; g_w[o+2] = r2 * inv;
}

// ---------------- gather + weighted interpolation ----------------
__global__ void interp_kernel(const float* __restrict__ points2)
{
    int lane = threadIdx.x & 31;
    int warp = threadIdx.x >> 5;
    size_t ng = (size_t)blockIdx.x * 8 + warp;
    int b = (int)(ng >> 12);

    const int*   id = g_idx + ng * 3;
    const float* wt = g_w   + ng * 3;
    int a0 = id[0], a1 = id[1], a2 = id[2];
    float w0 = wt[0], w1 = wt[1], w2 = wt[2];

    const float* P  = points2 + (size_t)b * S_ * C_;
    const float* p0 = P + (size_t)a0 * C_;
    const float* p1 = P + (size_t)a1 * C_;
    const float* p2 = P + (size_t)a2 * C_;
    float* out = g_interp + ng * C_;

    #pragma unroll
    for (int c = lane * 4; c < C_; c += 128) {
        float4 v0 = *(const float4*)(p0 + c);
        float4 v1 = *(const float4*)(p1 + c);
        float4 v2 = *(const float4*)(p2 + c);
        float4 o;
        o.x = w0*v0.x + w1*v1.x + w2*v2.x;
        o.y = w0*v0.y + w1*v1.y + w2*v2.y;
        o.z = w0*v0.z + w1*v1.z + w2*v2.z;
        o.w = w0*v0.w + w1*v1.w + w2*v2.w;
        *(float4*)(out + c) = o;
    }
}

// ---------------- tf32 mma.sync GEMM ----------------
// Y[m, n] = sum_k A[m, k] * W[n, k].  CTA tile 128x128, K chunks of 32.
// MODE 1: A = [points1 | g_interp] (K=512), Y = g_y (raw pre-BN)
// MODE 2: A = relu(bn1(g_y)) fused at fragment load (K=256), Y = d_out
// smem floats: A0[128*36] A1 B0[128*36] B1 scale[256] shift[256]
#define GSM_FLOATS (4 * 128 * 36 + 512)
#define GSM_BYTES  (GSM_FLOATS * 4)

template<int MODE>
__global__ __launch_bounds__(256, 2)
void gemm_mma_kernel(const float* __restrict__ Aext,
                     const float* __restrict__ W,
                     float* __restrict__ Yext)
{
    extern __shared__ __align__(16) float smem[];
    float* Abuf[2] = { smem,        smem + 4608 };
    float* Bbuf[2] = { smem + 9216, smem + 13824 };
    float* s_scale = smem + 18432;
    float* s_shift = s_scale + 256;

    const int NCH = (MODE == 1) ? 16 : 8;
    const int KW  = (MODE == 1) ? 512 : 256;
    float* Y = (MODE == 1) ? (float*)g_y : Yext;

    const int tid  = threadIdx.x;
    const int lane = tid & 31;
    const int wid  = tid >> 5;
    const int wm   = wid & 3;          // 4 warps along m (32 rows each)
    const int wn   = wid >> 2;         // 2 warps along n (64 cols each)
    const int m0   = blockIdx.y * 128;
    const int n0   = blockIdx.x * 128;

    if (MODE == 2 && tid < 256) {
        s_scale[tid] = g_scale[tid];
        s_shift[tid] = g_shift[tid];
    }

    const uint32_t sA[2] = { smem_u32(Abuf[0]), smem_u32(Abuf[1]) };
    const uint32_t sB[2] = { smem_u32(Bbuf[0]), smem_u32(Bbuf[1]) };
    const int lrow = tid >> 3;       // base row for this thread's first ld
    const int lc4  = tid & 7;        // 16B column group

    // issue cp.async for chunk kt into buffer buf
    auto cp_chunk = [&](int kt, int buf) {
        const float* Asrc; int acol;
        if (MODE == 1) {
            if (kt < 8) { Asrc = Aext;                    acol = kt * 32; }
            else        { Asrc = (const float*)g_interp;  acol = (kt - 8) * 32; }
        } else          { Asrc = (const float*)g_y;       acol = kt * 32; }
        const int kcol = kt * 32;
        #pragma unroll
        for (int i = 0; i < 4; i++) {
            int row = lrow + i * 32;
            uint32_t soff = (uint32_t)(row * 144 + lc4 * 16);
            CP16(sA[buf] + soff, Asrc + (size_t)(m0 + row) * C_ + acol + lc4 * 4);
            CP16(sB[buf] + soff, W    + (size_t)(n0 + row) * KW + kcol + lc4 * 4);
        }
        CP_COMMIT();
    };

    float c[2][8][4];
    #pragma unroll
    for (int mt = 0; mt < 2; mt++)
        #pragma unroll
        for (int nt = 0; nt < 8; nt++)
            #pragma unroll
            for (int j = 0; j < 4; j++) c[mt][nt][j] = 0.f;

    cp_chunk(0, 0);

    const int qk = lane & 3;     // k offset within frag
    const int qr = lane >> 2;    // row offset within frag

    for (int kt = 0; kt < NCH; kt++) {
        int buf = kt & 1;
        if (kt + 1 < NCH) { cp_chunk(kt + 1, buf ^ 1); CP_WAIT(1); }
        else              { CP_WAIT(0); }
        __syncthreads();

        const float* A_s = Abuf[buf];
        const float* B_s = Bbuf[buf];

        #pragma unroll
        for (int ks = 0; ks < 4; ks++) {
            const int k0 = ks * 8 + qk;
            uint32_t a[2][4];
            #pragma unroll
            for (int mt = 0; mt < 2; mt++) {
                int r = wm * 32 + mt * 16 + qr;
                float v0 = A_s[r * 36 + k0];
                float v1 = A_s[(r + 8) * 36 + k0];
                float v2 = A_s[r * 36 + k0 + 4];
                float v3 = A_s[(r + 8) * 36 + k0 + 4];
                if (MODE == 2) {
                    int ch0 = kt * 32 + ks * 8 + qk;
                    int ch1 = ch0 + 4;
                    float sc0 = s_scale[ch0], sh0 = s_shift[ch0];
                    float sc1 = s_scale[ch1], sh1 = s_shift[ch1];
                    v0 = fmaxf(fmaf(v0, sc0, sh0), 0.f);
                    v1 = fmaxf(fmaf(v1, sc0, sh0), 0.f);
                    v2 = fmaxf(fmaf(v2, sc1, sh1), 0.f);
                    v3 = fmaxf(fmaf(v3, sc1, sh1), 0.f);
                }
                a[mt][0] = f2tf(v0); a[mt][1] = f2tf(v1);
                a[mt][2] = f2tf(v2); a[mt][3] = f2tf(v3);
            }
            uint32_t b[8][2];
            #pragma unroll
            for (int nt = 0; nt < 8; nt++) {
                int r = wn * 64 + nt * 8 + qr;
                b[nt][0] = f2tf(B_s[r * 36 + k0]);
                b[nt][1] = f2tf(B_s[r * 36 + k0 + 4]);
            }
            #pragma unroll
            for (int mt = 0; mt < 2; mt++)
                #pragma unroll
                for (int nt = 0; nt < 8; nt++)
                    MMA_TF32(c[mt][nt], a[mt], b[nt]);
        }
        __syncthreads();
    }

    // epilogue: registers -> Y
    #pragma unroll
    for (int mt = 0; mt < 2; mt++) {
        int row = m0 + wm * 32 + mt * 16 + qr;
        #pragma unroll
        for (int nt = 0; nt < 8; nt++) {
            int col = n0 + wn * 64 + nt * 8 + 2 * qk;
            *(float2*)&Y[(size_t)row * 256 + col] =
                make_float2(c[mt][nt][0], c[mt][nt][1]);
            *(float2*)&Y[(size_t)(row + 8) * 256 + col] =
                make_float2(c[mt][nt][2], c[mt][nt][3]);
        }
    }
}

// ---------------- deterministic BatchNorm stats ----------------
template<bool USE_G>
__global__ void stats_partial_kernel(const float* Yext)
{
    const float* Y = USE_G ? (const float*)g_y : Yext;
    int c = threadIdx.x;
    size_t r0 = (size_t)blockIdx.x * 128;
    const float* p = Y + r0 * 256 + c;
    float s = 0.f, s2 = 0.f;
    for (int i = 0; i < 128; i++) {
        float v = p[(size_t)i * 256];
        s += v;
        s2 = fmaf(v, v, s2);
    }
    g_psum[blockIdx.x * 256 + c] = s;
    g_psq [blockIdx.x * 256 + c] = s2;
}

__global__ void stats_finalize_kernel(const float* __restrict__ gamma,
                                      const float* __restrict__ beta)
{
    int c = threadIdx.x;
    float s = 0.f, s2 = 0.f;
    for (int i = 0; i < 512; i++) {
        s  += g_psum[i * 256 + c];
        s2 += g_psq [i * 256 + c];
    }
    const float invM = 1.0f / 65536.0f;
    float mu   = s * invM;
    float var  = fmaf(-mu, mu, s2 * invM);
    float rstd = rsqrtf(var + 1e-5f);
    float sc   = rstd * gamma[c];
    g_scale[c] = sc;
    g_shift[c] = fmaf(-mu, sc, beta[c]);
}

__global__ void norm_relu_kernel(float* Y)
{
    size_t i = (size_t)blockIdx.x * blockDim.x + threadIdx.x;  // float4 index
    int cg = (int)(i & 63) * 4;
    float4 v = *((float4*)Y + i);
    v.x = fmaxf(fmaf(v.x, __ldg(&g_scale[cg+0]), __ldg(&g_shift[cg+0])), 0.f);
    v.y = fmaxf(fmaf(v.y, __ldg(&g_scale[cg+1]), __ldg(&g_shift[cg+1])), 0.f);
    v.z = fmaxf(fmaf(v.z, __ldg(&g_scale[cg+2]), __ldg(&g_shift[cg+2])), 0.f);
    v.w = fmaxf(fmaf(v.w, __ldg(&g_scale[cg+3]), __ldg(&g_shift[cg+3])), 0.f);
    *((float4*)Y + i) = v;
}

// ---------------- launch ----------------
extern "C" void kernel_launch(void* const* d_in, const int* in_sizes, int n_in,
                              void* d_out, int out_size)
{
    const float* xyz1    = (const float*)d_in[0];
    const float* xyz2    = (const float*)d_in[1];
    const float* points1 = (const float*)d_in[2];
    const float* points2 = (const float*)d_in[3];
    const float* w1      = (const float*)d_in[4];
    const float* g1      = (const float*)d_in[5];
    const float* b1      = (const float*)d_in[6];
    const float* w2      = (const float*)d_in[7];
    const float* g2      = (const float*)d_in[8];
    const float* b2      = (const float*)d_in[9];
    float* out = (float*)d_out;

    cudaFuncSetAttribute(gemm_mma_kernel<1>, cudaFuncAttributeMaxDynamicSharedMemorySize, GSM_BYTES);
    cudaFuncSetAttribute(gemm_mma_kernel<2>, cudaFuncAttributeMaxDynamicSharedMemorySize, GSM_BYTES);

    knn_kernel<<<dim3(N_ / 256, B_), 256>>>(xyz1, xyz2);
    interp_kernel<<<M_ / 8, 256>>>(points2);

    gemm_mma_kernel<1><<<dim3(2, 512), 256, GSM_BYTES>>>(points1, w1, nullptr);
    stats_partial_kernel<true><<<512, 256>>>(nullptr);
    stats_finalize_kernel<<<1, 256>>>(g1, b1);

    // layer-1 BN+ReLU fused into GEMM2's A-fragment load
    gemm_mma_kernel<2><<<dim3(2, 512), 256, GSM_BYTES>>>(nullptr, w2, out);
    stats_partial_kernel<false><<<512, 256>>>(out);
    stats_finalize_kernel<<<1, 256>>>(g2, b2);
    norm_relu_kernel<<<16384, 256>>>(out);
}

// round 9
// speedup vs baseline: 2.0779x; 1.0322x over previous
#include <cuda_runtime.h>
#include <cstdint>

#define B_  16
#define N_  4096
#define S_  1024
#define C_  256
#define M_  (B_ * N_)   // 65536

// ---------------- scratch (no allocations allowed) ----------------
__device__ float g_interp[(size_t)M_ * C_];   // (B*N, 256) interpolated feats (tf32-rounded)
__device__ float g_y[(size_t)M_ * C_];        // GEMM1 output (pre-BN hidden)
__device__ float g_w1t[256 * 512];            // w1 pre-rounded to tf32
__device__ float g_w2t[256 * 256];            // w2 pre-rounded to tf32
__device__ int   g_idx[M_ * 3];
__device__ float g_w[M_ * 3];
__device__ float g_psum[512 * 256];
__device__ float g_psq [512 * 256];
__device__ float g_scale[256];
__device__ float g_shift[256];

// ---------------- PTX helpers (family-portable, sm_80+) ----------------
__device__ __forceinline__ uint32_t smem_u32(const void* p) {
    uint32_t a;
    asm("{ .reg .u64 t; cvta.to.shared.u64 t, %1; cvt.u32.u64 %0, t; }" : "=r"(a) : "l"(p));
    return a;
}
__device__ __forceinline__ uint32_t f2tf(float x) {
    uint32_t r; asm("cvt.rna.tf32.f32 %0, %1;" : "=r"(r) : "f"(x)); return r;
}
#define CP16(dst, src) \
    asm volatile("cp.async.cg.shared.global [%0], [%1], 16;" :: "r"(dst), "l"(src) : "memory")
#define CP_COMMIT() asm volatile("cp.async.commit_group;" ::: "memory")
#define CP_WAIT(N)  asm volatile("cp.async.wait_group %0;" :: "n"(N) : "memory")

#define MMA_TF32(c, a, b) \
    asm volatile("mma.sync.aligned.m16n8k8.row.col.f32.tf32.tf32.f32 " \
        "{%0,%1,%2,%3}, {%4,%5,%6,%7}, {%8,%9}, {%0,%1,%2,%3};" \
        : "+f"((c)[0]), "+f"((c)[1]), "+f"((c)[2]), "+f"((c)[3]) \
        : "r"((a)[0]), "r"((a)[1]), "r"((a)[2]), "r"((a)[3]), \
          "r"((b)[0]), "r"((b)[1]))

// ---------------- prep: round weights to tf32 once ----------------
__global__ void prep_w_kernel(const float* __restrict__ w1,
                              const float* __restrict__ w2)
{
    int i = blockIdx.x * blockDim.x + threadIdx.x;
    if (i < 256 * 512) g_w1t[i] = __uint_as_float(f2tf(w1[i]));
    int j = i - 256 * 512;
    if (j >= 0 && j < 256 * 256) g_w2t[j] = __uint_as_float(f2tf(w2[j]));
}

// ---------------- 3-NN (idx + weights) ----------------
__global__ void knn_kernel(const float* __restrict__ xyz1,
                           const float* __restrict__ xyz2)
{
    __shared__ __align__(16) float4 sp[S_];
    int b = blockIdx.y;
    const float* X2 = xyz2 + (size_t)b * S_ * 3;
    for (int i = threadIdx.x; i < S_; i += blockDim.x) {
        float x = X2[i*3+0], y = X2[i*3+1], z = X2[i*3+2];
        sp[i] = make_float4(x, y, z, x*x + y*y + z*z);
    }
    __syncthreads();

    int n = blockIdx.x * blockDim.x + threadIdx.x;
    const float* p = xyz1 + ((size_t)b * N_ + n) * 3;
    float x1 = p[0], y1 = p[1], z1 = p[2];
    float s1 = x1*x1 + y1*y1 + z1*z1;

    float d0 = 3.4e38f, d1 = 3.4e38f, d2 = 3.4e38f;
    int   i0 = 0, i1 = 0, i2 = 0;
    #pragma unroll 4
    for (int s = 0; s < S_; s++) {
        float4 q = sp[s];
        float dot = fmaf(x1, q.x, fmaf(y1, q.y, z1 * q.z));
        float d   = fmaf(-2.0f, dot, s1 + q.w);
        if (d < d2) {
            if (d < d1) {
                d2 = d1; i2 = i1;
                if (d < d0) { d1 = d0; i1 = i0; d0 = d; i0 = s; }
                else        { d1 = d;  i1 = s; }
            } else { d2 = d; i2 = s; }
        }
    }
    float r0 = 1.0f / (d0 + 1e-8f);
    float r1 = 1.0f / (d1 + 1e-8f);
    float r2 = 1.0f / (d2 + 1e-8f);
    float inv = 1.0f / (r0 + r1 + r2);
    size_t o = ((size_t)b * N_ + n) * 3;
    g_idx[o+0] = i0; g_idx[o+1] = i1; g_idx[o+2] = i2;
    g_w[o+0] = r0 * inv; g_w[o+1] = r1 * inv; g_w[o+2] = r2 * inv;
}

// ---------------- gather + weighted interpolation (tf32-rounded out) ----------------
__global__ void interp_kernel(const float* __restrict__ points2)
{
    int lane = threadIdx.x & 31;
    int warp = threadIdx.x >> 5;
    size_t ng = (size_t)blockIdx.x * 8 + warp;
    int b = (int)(ng >> 12);

    const int*   id = g_idx + ng * 3;
    const float* wt = g_w   + ng * 3;
    int a0 = id[0], a1 = id[1], a2 = id[2];
    float w0 = wt[0], w1 = wt[1], w2 = wt[2];

    const float* P  = points2 + (size_t)b * S_ * C_;
    const float* p0 = P + (size_t)a0 * C_;
    const float* p1 = P + (size_t)a1 * C_;
    const float* p2 = P + (size_t)a2 * C_;
    float* out = g_interp + ng * C_;

    #pragma unroll
    for (int c = lane * 4; c < C_; c += 128) {
        float4 v0 = *(const float4*)(p0 + c);
        float4 v1 = *(const float4*)(p1 + c);
        float4 v2 = *(const float4*)(p2 + c);
        float4 o;
        o.x = __uint_as_float(f2tf(w0*v0.x + w1*v1.x + w2*v2.x));
        o.y = __uint_as_float(f2tf(w0*v0.y + w1*v1.y + w2*v2.y));
        o.z = __uint_as_float(f2tf(w0*v0.z + w1*v1.z + w2*v2.z));
        o.w = __uint_as_float(f2tf(w0*v0.w + w1*v1.w + w2*v2.w));
        *(float4*)(out + c) = o;
    }
}

// ---------------- tf32 mma.sync GEMM + fused BN-stats epilogue ----------------
// Y[m, n] = sum_k A[m, k] * W[n, k].  CTA tile 128x128, K chunks of 32.
// MODE 1: A = [points1 | g_interp] (K=512), W = g_w1t, Y = g_y
// MODE 2: A = relu(bn1(g_y)) fused at fragment load (K=256), W = g_w2t, Y = d_out
// Epilogue also writes per-CTA column partial sum/sumsq -> g_psum/g_psq.
#define GSM_FLOATS (4 * 128 * 36 + 512)
#define GSM_BYTES  (GSM_FLOATS * 4)

template<int MODE>
__global__ __launch_bounds__(256, 2)
void gemm_mma_kernel(const float* __restrict__ Aext,
                     float* __restrict__ Yext)
{
    extern __shared__ __align__(16) float smem[];
    float* Abuf[2] = { smem,        smem + 4608 };
    float* Bbuf[2] = { smem + 9216, smem + 13824 };
    float* s_scale = smem + 18432;
    float* s_shift = s_scale + 256;

    const int NCH = (MODE == 1) ? 16 : 8;
    const int KW  = (MODE == 1) ? 512 : 256;
    const float* W = (MODE == 1) ? (const float*)g_w1t : (const float*)g_w2t;
    float* Y = (MODE == 1) ? (float*)g_y : Yext;

    const int tid  = threadIdx.x;
    const int lane = tid & 31;
    const int wid  = tid >> 5;
    const int wm   = wid & 3;          // 4 warps along m (32 rows each)
    const int wn   = wid >> 2;         // 2 warps along n (64 cols each)
    const int m0   = blockIdx.y * 128;
    const int n0   = blockIdx.x * 128;

    if (MODE == 2 && tid < 256) {
        s_scale[tid] = g_scale[tid];
        s_shift[tid] = g_shift[tid];
    }

    const uint32_t sA[2] = { smem_u32(Abuf[0]), smem_u32(Abuf[1]) };
    const uint32_t sB[2] = { smem_u32(Bbuf[0]), smem_u32(Bbuf[1]) };
    const int lrow = tid >> 3;
    const int lc4  = tid & 7;

    auto cp_chunk = [&](int kt, int buf) {
        const float* Asrc; int acol;
        if (MODE == 1) {
            if (kt < 8) { Asrc = Aext;                    acol = kt * 32; }
            else        { Asrc = (const float*)g_interp;  acol = (kt - 8) * 32; }
        } else          { Asrc = (const float*)g_y;       acol = kt * 32; }
        const int kcol = kt * 32;
        #pragma unroll
        for (int i = 0; i < 4; i++) {
            int row = lrow + i * 32;
            uint32_t soff = (uint32_t)(row * 144 + lc4 * 16);
            CP16(sA[buf] + soff, Asrc + (size_t)(m0 + row) * C_ + acol + lc4 * 4);
            CP16(sB[buf] + soff, W    + (size_t)(n0 + row) * KW + kcol + lc4 * 4);
        }
        CP_COMMIT();
    };

    float c[2][8][4];
    #pragma unroll
    for (int mt = 0; mt < 2; mt++)
        #pragma unroll
        for (int nt = 0; nt < 8; nt++)
            #pragma unroll
            for (int j = 0; j < 4; j++) c[mt][nt][j] = 0.f;

    cp_chunk(0, 0);

    const int qk = lane & 3;     // k offset within frag
    const int qr = lane >> 2;    // row offset within frag

    for (int kt = 0; kt < NCH; kt++) {
        int buf = kt & 1;
        if (kt + 1 < NCH) { cp_chunk(kt + 1, buf ^ 1); CP_WAIT(1); }
        else              { CP_WAIT(0); }
        __syncthreads();

        const float* A_s = Abuf[buf];
        const float* B_s = Bbuf[buf];

        #pragma unroll
        for (int ks = 0; ks < 4; ks++) {
            const int k0 = ks * 8 + qk;
            uint32_t a[2][4];
            #pragma unroll
            for (int mt = 0; mt < 2; mt++) {
                int r = wm * 32 + mt * 16 + qr;
                float v0 = A_s[r * 36 + k0];
                float v1 = A_s[(r + 8) * 36 + k0];
                float v2 = A_s[r * 36 + k0 + 4];
                float v3 = A_s[(r + 8) * 36 + k0 + 4];
                if (MODE == 2) {
                    int ch0 = kt * 32 + ks * 8 + qk;
                    int ch1 = ch0 + 4;
                    float sc0 = s_scale[ch0], sh0 = s_shift[ch0];
                    float sc1 = s_scale[ch1], sh1 = s_shift[ch1];
                    v0 = fmaxf(fmaf(v0, sc0, sh0), 0.f);
                    v1 = fmaxf(fmaf(v1, sc0, sh0), 0.f);
                    v2 = fmaxf(fmaf(v2, sc1, sh1), 0.f);
                    v3 = fmaxf(fmaf(v3, sc1, sh1), 0.f);
                }
                a[mt][0] = f2tf(v0); a[mt][1] = f2tf(v1);
                a[mt][2] = f2tf(v2); a[mt][3] = f2tf(v3);
            }
            uint32_t b[8][2];
            #pragma unroll
            for (int nt = 0; nt < 8; nt++) {
                int r = wn * 64 + nt * 8 + qr;
                b[nt][0] = __float_as_uint(B_s[r * 36 + k0]);       // pre-rounded tf32
                b[nt][1] = __float_as_uint(B_s[r * 36 + k0 + 4]);
            }
            #pragma unroll
            for (int mt = 0; mt < 2; mt++)
                #pragma unroll
                for (int nt = 0; nt < 8; nt++)
                    MMA_TF32(c[mt][nt], a[mt], b[nt]);
        }
        __syncthreads();
    }

    // ---- epilogue: write Y ----
    #pragma unroll
    for (int mt = 0; mt < 2; mt++) {
        int row = m0 + wm * 32 + mt * 16 + qr;
        #pragma unroll
        for (int nt = 0; nt < 8; nt++) {
            int col = n0 + wn * 64 + nt * 8 + 2 * qk;
            *(float2*)&Y[(size_t)row * 256 + col] =
                make_float2(c[mt][nt][0], c[mt][nt][1]);
            *(float2*)&Y[(size_t)(row + 8) * 256 + col] =
                make_float2(c[mt][nt][2], c[mt][nt][3]);
        }
    }

    // ---- fused BN stats: per-column partial sum / sumsq over this CTA's 128 rows ----
    // smem is free after the final __syncthreads of the main loop.
    float* s_sum = smem;         // [4][128]
    float* s_sq  = smem + 512;   // [4][128]
    #pragma unroll
    for (int nt = 0; nt < 8; nt++) {
        #pragma unroll
        for (int p = 0; p < 2; p++) {
            float v0 = c[0][nt][p],     v1 = c[0][nt][p + 2];
            float v2 = c[1][nt][p],     v3 = c[1][nt][p + 2];
            float s  = (v0 + v1) + (v2 + v3);
            float s2 = fmaf(v0, v0, fmaf(v1, v1, fmaf(v2, v2, v3 * v3)));
            #pragma unroll
            for (int off = 4; off <= 16; off <<= 1) {
                s  += __shfl_xor_sync(0xFFFFFFFFu, s,  off);
                s2 += __shfl_xor_sync(0xFFFFFFFFu, s2, off);
            }
            if (qr == 0) {
                int col = wn * 64 + nt * 8 + 2 * qk + p;   // 0..127
                s_sum[wm * 128 + col] = s;
                s_sq [wm * 128 + col] = s2;
            }
        }
    }
    __syncthreads();
    if (tid < 128) {
        int col = tid;
        float s  = (s_sum[col] + s_sum[128 + col]) + (s_sum[256 + col] + s_sum[384 + col]);
        float s2 = (s_sq [col] + s_sq [128 + col]) + (s_sq [256 + col] + s_sq [384 + col]);
        size_t slot = (size_t)blockIdx.y * 256 + blockIdx.x * 128 + col;
        g_psum[slot] = s;
        g_psq [slot] = s2;
    }
}

// ---------------- BN finalize ----------------
__global__ void stats_finalize_kernel(const float* __restrict__ gamma,
                                      const float* __restrict__ beta)
{
    int c = threadIdx.x;
    float s = 0.f, s2 = 0.f;
    for (int i = 0; i < 512; i++) {
        s  += g_psum[i * 256 + c];
        s2 += g_psq [i * 256 + c];
    }
    const float invM = 1.0f / 65536.0f;
    float mu   = s * invM;
    float var  = fmaf(-mu, mu, s2 * invM);
    float rstd = rsqrtf(var + 1e-5f);
    float sc   = rstd * gamma[c];
    g_scale[c] = sc;
    g_shift[c] = fmaf(-mu, sc, beta[c]);
}

__global__ void norm_relu_kernel(float* Y)
{
    size_t i = (size_t)blockIdx.x * blockDim.x + threadIdx.x;  // float4 index
    int cg = (int)(i & 63) * 4;
    float4 v = *((float4*)Y + i);
    v.x = fmaxf(fmaf(v.x, __ldg(&g_scale[cg+0]), __ldg(&g_shift[cg+0])), 0.f);
    v.y = fmaxf(fmaf(v.y, __ldg(&g_scale[cg+1]), __ldg(&g_shift[cg+1])), 0.f);
    v.z = fmaxf(fmaf(v.z, __ldg(&g_scale[cg+2]), __ldg(&g_shift[cg+2])), 0.f);
    v.w = fmaxf(fmaf(v.w, __ldg(&g_scale[cg+3]), __ldg(&g_shift[cg+3])), 0.f);
    *((float4*)Y + i) = v;
}

// ---------------- launch ----------------
extern "C" void kernel_launch(void* const* d_in, const int* in_sizes, int n_in,
                              void* d_out, int out_size)
{
    const float* xyz1    = (const float*)d_in[0];
    const float* xyz2    = (const float*)d_in[1];
    const float* points1 = (const float*)d_in[2];
    const float* points2 = (const float*)d_in[3];
    const float* w1      = (const float*)d_in[4];
    const float* g1      = (const float*)d_in[5];
    const float* b1      = (const float*)d_in[6];
    const float* w2      = (const float*)d_in[7];
    const float* g2      = (const float*)d_in[8];
    const float* b2      = (const float*)d_in[9];
    float* out = (float*)d_out;

    cudaFuncSetAttribute(gemm_mma_kernel<1>, cudaFuncAttributeMaxDynamicSharedMemorySize, GSM_BYTES);
    cudaFuncSetAttribute(gemm_mma_kernel<2>, cudaFuncAttributeMaxDynamicSharedMemorySize, GSM_BYTES);

    prep_w_kernel<<<768, 256>>>(w1, w2);
    knn_kernel<<<dim3(N_ / 256, B_), 256>>>(xyz1, xyz2);
    interp_kernel<<<M_ / 8, 256>>>(points2);

    gemm_mma_kernel<1><<<dim3(2, 512), 256, GSM_BYTES>>>(points1, nullptr);   // + stats
    stats_finalize_kernel<<<1, 256>>>(g1, b1);

    gemm_mma_kernel<2><<<dim3(2, 512), 256, GSM_BYTES>>>(nullptr, out);       // + stats
    stats_finalize_kernel<<<1, 256>>>(g2, b2);
    norm_relu_kernel<<<16384, 256>>>(out);
}

// round 10
// speedup vs baseline: 2.2581x; 1.0867x over previous
#include <cuda_runtime.h>
#include <cstdint>

#define B_  16
#define N_  4096
#define S_  1024
#define C_  256
#define M_  (B_ * N_)   // 65536

// ---------------- scratch (no allocations allowed) ----------------
__device__ float g_interp[(size_t)M_ * C_];   // (B*N, 256) interpolated feats (tf32-rounded)
__device__ float g_y[(size_t)M_ * C_];        // GEMM1 output (pre-BN hidden)
__device__ float g_w1t[256 * 512];            // w1 pre-rounded to tf32
__device__ float g_w2t[256 * 256];            // w2 pre-rounded to tf32
__device__ int   g_idx[M_ * 3];
__device__ float g_w[M_ * 3];
__device__ float g_psum[512 * 256];
__device__ float g_psq [512 * 256];
__device__ float g_scale[256];
__device__ float g_shift[256];

// ---------------- PTX helpers (family-portable, sm_80+) ----------------
__device__ __forceinline__ uint32_t smem_u32(const void* p) {
    uint32_t a;
    asm("{ .reg .u64 t; cvta.to.shared.u64 t, %1; cvt.u32.u64 %0, t; }" : "=r"(a) : "l"(p));
    return a;
}
__device__ __forceinline__ uint32_t f2tf(float x) {
    uint32_t r; asm("cvt.rna.tf32.f32 %0, %1;" : "=r"(r) : "f"(x)); return r;
}
#define CP16(dst, src) \
    asm volatile("cp.async.cg.shared.global [%0], [%1], 16;" :: "r"(dst), "l"(src) : "memory")
#define CP_COMMIT() asm volatile("cp.async.commit_group;" ::: "memory")
#define CP_WAIT(N)  asm volatile("cp.async.wait_group %0;" :: "n"(N) : "memory")

#define MMA_TF32(c, a, b) \
    asm volatile("mma.sync.aligned.m16n8k8.row.col.f32.tf32.tf32.f32 " \
        "{%0,%1,%2,%3}, {%4,%5,%6,%7}, {%8,%9}, {%0,%1,%2,%3};" \
        : "+f"((c)[0]), "+f"((c)[1]), "+f"((c)[2]), "+f"((c)[3]) \
        : "r"((a)[0]), "r"((a)[1]), "r"((a)[2]), "r"((a)[3]), \
          "r"((b)[0]), "r"((b)[1]))

// ldmatrix x4 on b16 tiles == four 8x4 tf32 tiles; thread t gets tf32 (row t/4, col t%4)
#define LDSM4(r0, r1, r2, r3, addr) \
    asm volatile("ldmatrix.sync.aligned.m8n8.x4.shared.b16 {%0,%1,%2,%3}, [%4];" \
        : "=r"(r0), "=r"(r1), "=r"(r2), "=r"(r3) : "r"(addr))

// ---------------- prep: round weights to tf32 once ----------------
__global__ void prep_w_kernel(const float* __restrict__ w1,
                              const float* __restrict__ w2)
{
    int i = blockIdx.x * blockDim.x + threadIdx.x;
    if (i < 256 * 512) g_w1t[i] = __uint_as_float(f2tf(w1[i]));
    int j = i - 256 * 512;
    if (j >= 0 && j < 256 * 256) g_w2t[j] = __uint_as_float(f2tf(w2[j]));
}

// ---------------- 3-NN (idx + weights) ----------------
__global__ void knn_kernel(const float* __restrict__ xyz1,
                           const float* __restrict__ xyz2)
{
    __shared__ __align__(16) float4 sp[S_];
    int b = blockIdx.y;
    const float* X2 = xyz2 + (size_t)b * S_ * 3;
    for (int i = threadIdx.x; i < S_; i += blockDim.x) {
        float x = X2[i*3+0], y = X2[i*3+1], z = X2[i*3+2];
        sp[i] = make_float4(x, y, z, x*x + y*y + z*z);
    }
    __syncthreads();

    int n = blockIdx.x * blockDim.x + threadIdx.x;
    const float* p = xyz1 + ((size_t)b * N_ + n) * 3;
    float x1 = p[0], y1 = p[1], z1 = p[2];
    float s1 = x1*x1 + y1*y1 + z1*z1;

    float d0 = 3.4e38f, d1 = 3.4e38f, d2 = 3.4e38f;
    int   i0 = 0, i1 = 0, i2 = 0;
    #pragma unroll 4
    for (int s = 0; s < S_; s++) {
        float4 q = sp[s];
        float dot = fmaf(x1, q.x, fmaf(y1, q.y, z1 * q.z));
        float d   = fmaf(-2.0f, dot, s1 + q.w);
        if (d < d2) {
            if (d < d1) {
                d2 = d1; i2 = i1;
                if (d < d0) { d1 = d0; i1 = i0; d0 = d; i0 = s; }
                else        { d1 = d;  i1 = s; }
            } else { d2 = d; i2 = s; }
        }
    }
    float r0 = 1.0f / (d0 + 1e-8f);
    float r1 = 1.0f / (d1 + 1e-8f);
    float r2 = 1.0f / (d2 + 1e-8f);
    float inv = 1.0f / (r0 + r1 + r2);
    size_t o = ((size_t)b * N_ + n) * 3;
    g_idx[o+0] = i0; g_idx[o+1] = i1; g_idx[o+2] = i2;
    g_w[o+0] = r0 * inv; g_w[o+1] = r1 * inv; g_w[o+2] = r2 * inv;
}

// ---------------- gather + weighted interpolation (tf32-rounded out) ----------------
__global__ void interp_kernel(const float* __restrict__ points2)
{
    int lane = threadIdx.x & 31;
    int warp = threadIdx.x >> 5;
    size_t ng = (size_t)blockIdx.x * 8 + warp;
    int b = (int)(ng >> 12);

    const int*   id = g_idx + ng * 3;
    const float* wt = g_w   + ng * 3;
    int a0 = id[0], a1 = id[1], a2 = id[2];
    float w0 = wt[0], w1 = wt[1], w2 = wt[2];

    const float* P  = points2 + (size_t)b * S_ * C_;
    const float* p0 = P + (size_t)a0 * C_;
    const float* p1 = P + (size_t)a1 * C_;
    const float* p2 = P + (size_t)a2 * C_;
    float* out = g_interp + ng * C_;

    #pragma unroll
    for (int c = lane * 4; c < C_; c += 128) {
        float4 v0 = *(const float4*)(p0 + c);
        float4 v1 = *(const float4*)(p1 + c);
        float4 v2 = *(const float4*)(p2 + c);
        float4 o;
        o.x = __uint_as_float(f2tf(w0*v0.x + w1*v1.x + w2*v2.x));
        o.y = __uint_as_float(f2tf(w0*v0.y + w1*v1.y + w2*v2.y));
        o.z = __uint_as_float(f2tf(w0*v0.z + w1*v1.z + w2*v2.z));
        o.w = __uint_as_float(f2tf(w0*v0.w + w1*v1.w + w2*v2.w));
        *(float4*)(out + c) = o;
    }
}

// ---------------- tf32 mma.sync GEMM (ldmatrix fragments) + fused BN-stats ----------------
// Y[m, n] = sum_k A[m, k] * W[n, k].  CTA tile 128x128, K chunks of 32.
// MODE 1: A = [points1 | g_interp] (K=512), W = g_w1t, Y = g_y
// MODE 2: A = relu(bn1(g_y)) fused at fragment load (K=256), W = g_w2t, Y = d_out
#define GSM_FLOATS (4 * 128 * 36 + 512)
#define GSM_BYTES  (GSM_FLOATS * 4)

template<int MODE>
__global__ __launch_bounds__(256, 2)
void gemm_mma_kernel(const float* __restrict__ Aext,
                     float* __restrict__ Yext)
{
    extern __shared__ __align__(16) float smem[];
    float* Abuf[2] = { smem,        smem + 4608 };
    float* Bbuf[2] = { smem + 9216, smem + 13824 };
    float* s_scale = smem + 18432;
    float* s_shift = s_scale + 256;

    const int NCH = (MODE == 1) ? 16 : 8;
    const int KW  = (MODE == 1) ? 512 : 256;
    const float* W = (MODE == 1) ? (const float*)g_w1t : (const float*)g_w2t;
    float* Y = (MODE == 1) ? (float*)g_y : Yext;

    const int tid  = threadIdx.x;
    const int lane = tid & 31;
    const int wid  = tid >> 5;
    const int wm   = wid & 3;          // 4 warps along m (32 rows each)
    const int wn   = wid >> 2;         // 2 warps along n (64 cols each)
    const int m0   = blockIdx.y * 128;
    const int n0   = blockIdx.x * 128;

    if (MODE == 2 && tid < 256) {
        s_scale[tid] = g_scale[tid];
        s_shift[tid] = g_shift[tid];
    }

    const uint32_t sA[2] = { smem_u32(Abuf[0]), smem_u32(Abuf[1]) };
    const uint32_t sB[2] = { smem_u32(Bbuf[0]), smem_u32(Bbuf[1]) };
    const int lrow = tid >> 3;
    const int lc4  = tid & 7;

    auto cp_chunk = [&](int kt, int buf) {
        const float* Asrc; int acol;
        if (MODE == 1) {
            if (kt < 8) { Asrc = Aext;                    acol = kt * 32; }
            else        { Asrc = (const float*)g_interp;  acol = (kt - 8) * 32; }
        } else          { Asrc = (const float*)g_y;       acol = kt * 32; }
        const int kcol = kt * 32;
        #pragma unroll
        for (int i = 0; i < 4; i++) {
            int row = lrow + i * 32;
            uint32_t soff = (uint32_t)(row * 144 + lc4 * 16);
            CP16(sA[buf] + soff, Asrc + (size_t)(m0 + row) * C_ + acol + lc4 * 4);
            CP16(sB[buf] + soff, W    + (size_t)(n0 + row) * KW + kcol + lc4 * 4);
        }
        CP_COMMIT();
    };

    float c[2][8][4];
    #pragma unroll
    for (int mt = 0; mt < 2; mt++)
        #pragma unroll
        for (int nt = 0; nt < 8; nt++)
            #pragma unroll
            for (int j = 0; j < 4; j++) c[mt][nt][j] = 0.f;

    cp_chunk(0, 0);

    const int qk = lane & 3;     // k offset within frag
    const int qr = lane >> 2;    // row offset within frag

    // ldmatrix per-lane source rows:
    //   A x4 tiles: T0 rows0-7/k0-3, T1 rows8-15/k0-3, T2 rows0-7/k4-7, T3 rows8-15/k4-7
    //   B x4 tiles: T0 nt rows/k0-3, T1 nt rows/k4-7, T2 nt+1/k0-3, T3 nt+1/k4-7
    const int lg = lane >> 3;            // tile index 0..3
    const int lr8 = lane & 7;            // row within tile
    const uint32_t aoff = (uint32_t)(((wm * 32 + (lg & 1) * 8 + lr8) * 36 + (lg >> 1) * 4) * 4);
    const uint32_t boff = (uint32_t)(((wn * 64 + (lg >> 1) * 8 + lr8) * 36 + (lg & 1) * 4) * 4);

    for (int kt = 0; kt < NCH; kt++) {
        int buf = kt & 1;
        if (kt + 1 < NCH) { cp_chunk(kt + 1, buf ^ 1); CP_WAIT(1); }
        else              { CP_WAIT(0); }
        __syncthreads();

        const uint32_t aBase = sA[buf] + aoff;
        const uint32_t bBase = sB[buf] + boff;

        #pragma unroll
        for (int ks = 0; ks < 4; ks++) {
            uint32_t a[2][4];
            #pragma unroll
            for (int mt = 0; mt < 2; mt++) {
                uint32_t r0, r1, r2, r3;
                LDSM4(r0, r1, r2, r3, aBase + mt * (16 * 144) + ks * 32);
                float v0 = __uint_as_float(r0), v1 = __uint_as_float(r1);
                float v2 = __uint_as_float(r2), v3 = __uint_as_float(r3);
                if (MODE == 2) {
                    int ch0 = kt * 32 + ks * 8 + qk;
                    int ch1 = ch0 + 4;
                    float sc0 = s_scale[ch0], sh0 = s_shift[ch0];
                    float sc1 = s_scale[ch1], sh1 = s_shift[ch1];
                    v0 = fmaxf(fmaf(v0, sc0, sh0), 0.f);
                    v1 = fmaxf(fmaf(v1, sc0, sh0), 0.f);
                    v2 = fmaxf(fmaf(v2, sc1, sh1), 0.f);
                    v3 = fmaxf(fmaf(v3, sc1, sh1), 0.f);
                }
                a[mt][0] = f2tf(v0); a[mt][1] = f2tf(v1);
                a[mt][2] = f2tf(v2); a[mt][3] = f2tf(v3);
            }
            uint32_t b[8][2];
            #pragma unroll
            for (int nt2 = 0; nt2 < 4; nt2++) {
                LDSM4(b[2*nt2][0], b[2*nt2][1], b[2*nt2+1][0], b[2*nt2+1][1],
                      bBase + nt2 * (16 * 144) + ks * 32);   // B pre-rounded tf32
            }
            #pragma unroll
            for (int mt = 0; mt < 2; mt++)
                #pragma unroll
                for (int nt = 0; nt < 8; nt++)
                    MMA_TF32(c[mt][nt], a[mt], b[nt]);
        }
        __syncthreads();
    }

    // ---- epilogue: write Y ----
    #pragma unroll
    for (int mt = 0; mt < 2; mt++) {
        int row = m0 + wm * 32 + mt * 16 + qr;
        #pragma unroll
        for (int nt = 0; nt < 8; nt++) {
            int col = n0 + wn * 64 + nt * 8 + 2 * qk;
            *(float2*)&Y[(size_t)row * 256 + col] =
                make_float2(c[mt][nt][0], c[mt][nt][1]);
            *(float2*)&Y[(size_t)(row + 8) * 256 + col] =
                make_float2(c[mt][nt][2], c[mt][nt][3]);
        }
    }

    // ---- fused BN stats: per-column partial sum / sumsq over this CTA's 128 rows ----
    float* s_sum = smem;         // [4][128]
    float* s_sq  = smem + 512;   // [4][128]
    #pragma unroll
    for (int nt = 0; nt < 8; nt++) {
        #pragma unroll
        for (int p = 0; p < 2; p++) {
            float v0 = c[0][nt][p],     v1 = c[0][nt][p + 2];
            float v2 = c[1][nt][p],     v3 = c[1][nt][p + 2];
            float s  = (v0 + v1) + (v2 + v3);
            float s2 = fmaf(v0, v0, fmaf(v1, v1, fmaf(v2, v2, v3 * v3)));
            #pragma unroll
            for (int off = 4; off <= 16; off <<= 1) {
                s  += __shfl_xor_sync(0xFFFFFFFFu, s,  off);
                s2 += __shfl_xor_sync(0xFFFFFFFFu, s2, off);
            }
            if (qr == 0) {
                int col = wn * 64 + nt * 8 + 2 * qk + p;   // 0..127
                s_sum[wm * 128 + col] = s;
                s_sq [wm * 128 + col] = s2;
            }
        }
    }
    __syncthreads();
    if (tid < 128) {
        int col = tid;
        float s  = (s_sum[col] + s_sum[128 + col]) + (s_sum[256 + col] + s_sum[384 + col]);
        float s2 = (s_sq [col] + s_sq [128 + col]) + (s_sq [256 + col] + s_sq [384 + col]);
        size_t slot = (size_t)blockIdx.y * 256 + blockIdx.x * 128 + col;
        g_psum[slot] = s;
        g_psq [slot] = s2;
    }
}

// ---------------- BN finalize ----------------
__global__ void stats_finalize_kernel(const float* __restrict__ gamma,
                                      const float* __restrict__ beta)
{
    int c = threadIdx.x;
    float s = 0.f, s2 = 0.f;
    for (int i = 0; i < 512; i++) {
        s  += g_psum[i * 256 + c];
        s2 += g_psq [i * 256 + c];
    }
    const float invM = 1.0f / 65536.0f;
    float mu   = s * invM;
    float var  = fmaf(-mu, mu, s2 * invM);
    float rstd = rsqrtf(var + 1e-5f);
    float sc   = rstd * gamma[c];
    g_scale[c] = sc;
    g_shift[c] = fmaf(-mu, sc, beta[c]);
}

__global__ void norm_relu_kernel(float* Y)
{
    size_t i = (size_t)blockIdx.x * blockDim.x + threadIdx.x;  // float4 index
    int cg = (int)(i & 63) * 4;
    float4 v = *((float4*)Y + i);
    v.x = fmaxf(fmaf(v.x, __ldg(&g_scale[cg+0]), __ldg(&g_shift[cg+0])), 0.f);
    v.y = fmaxf(fmaf(v.y, __ldg(&g_scale[cg+1]), __ldg(&g_shift[cg+1])), 0.f);
    v.z = fmaxf(fmaf(v.z, __ldg(&g_scale[cg+2]), __ldg(&g_shift[cg+2])), 0.f);
    v.w = fmaxf(fmaf(v.w, __ldg(&g_scale[cg+3]), __ldg(&g_shift[cg+3])), 0.f);
    *((float4*)Y + i) = v;
}

// ---------------- launch ----------------
extern "C" void kernel_launch(void* const* d_in, const int* in_sizes, int n_in,
                              void* d_out, int out_size)
{
    const float* xyz1    = (const float*)d_in[0];
    const float* xyz2    = (const float*)d_in[1];
    const float* points1 = (const float*)d_in[2];
    const float* points2 = (const float*)d_in[3];
    const float* w1      = (const float*)d_in[4];
    const float* g1      = (const float*)d_in[5];
    const float* b1      = (const float*)d_in[6];
    const float* w2      = (const float*)d_in[7];
    const float* g2      = (const float*)d_in[8];
    const float* b2      = (const float*)d_in[9];
    float* out = (float*)d_out;

    cudaFuncSetAttribute(gemm_mma_kernel<1>, cudaFuncAttributeMaxDynamicSharedMemorySize, GSM_BYTES);
    cudaFuncSetAttribute(gemm_mma_kernel<2>, cudaFuncAttributeMaxDynamicSharedMemorySize, GSM_BYTES);

    prep_w_kernel<<<768, 256>>>(w1, w2);
    knn_kernel<<<dim3(N_ / 256, B_), 256>>>(xyz1, xyz2);
    interp_kernel<<<M_ / 8, 256>>>(points2);

    gemm_mma_kernel<1><<<dim3(2, 512), 256, GSM_BYTES>>>(points1, nullptr);   // + stats
    stats_finalize_kernel<<<1, 256>>>(g1, b1);

    gemm_mma_kernel<2><<<dim3(2, 512), 256, GSM_BYTES>>>(nullptr, out);       // + stats
    stats_finalize_kernel<<<1, 256>>>(g2, b2);
    norm_relu_kernel<<<16384, 256>>>(out);
}